// round 1
// baseline (speedup 1.0000x reference)
#include <cuda_runtime.h>

#define BB    64
#define TXX   1024
#define AD    1024
#define UN    1024
#define VOC   32000
#define ED    512
#define KXIN  2560      // 1024 ctx + 512 emb + 1024 h
#define NZ    4096      // 4*UNITS

// ---------------- scratch (__device__ globals, no allocation) ----------------
__device__ float g_pctx[8 * BB * AD];        // 2 MB  partial context sums
__device__ float g_xinT[KXIN * BB];          // 640KB transposed [K][64] input for z-GEMM
__device__ float g_zpart[4 * BB * NZ];       // 4 MB  K-split partials of z
__device__ float g_hT[UN * BB];              // 256KB transposed h_new for logits GEMM
__device__ float g_lpart[2 * BB * VOC];      // 16 MB K-split partials of logits
__device__ float g_logits[BB * VOC];         // 8 MB  combined logits

// ---------------- packed fp32x2 helpers (2x FFMA throughput) ----------------
typedef unsigned long long ull;
__device__ __forceinline__ ull pack2(float lo, float hi) {
    ull r; asm("mov.b64 %0,{%1,%2};" : "=l"(r) : "f"(lo), "f"(hi)); return r;
}
__device__ __forceinline__ ull fma2(ull a, ull b, ull c) {
    ull d; asm("fma.rn.f32x2 %0,%1,%2,%3;" : "=l"(d) : "l"(a), "l"(b), "l"(c)); return d;
}
__device__ __forceinline__ float2 unpack2(ull v) {
    float lo, hi; asm("mov.b64 {%0,%1},%2;" : "=f"(lo), "=f"(hi) : "l"(v));
    float2 f; f.x = lo; f.y = hi; return f;
}
__device__ __forceinline__ float sigf(float x) { return 1.0f / (1.0f + __expf(-x)); }

// ---------------- K1: context partial sums ----------------
// alpha = softmax over size-1 axis == 1  =>  context[b,d] = sum_t a[b,t,d]
// grid (4 d-chunks, 8 t-chunks, 64 b), block 256
__global__ void ctx_partial(const float* __restrict__ a) {
    int d  = blockIdx.x * 256 + threadIdx.x;
    int b  = blockIdx.z;
    int t0 = blockIdx.y * 128;
    const float* p = a + ((size_t)b * TXX + t0) * AD + d;
    float s = 0.0f;
#pragma unroll 8
    for (int t = 0; t < 128; t++) s += p[(size_t)t * AD];
    g_pctx[((size_t)blockIdx.y * BB + b) * AD + d] = s;
}

// ---------------- K2: finalize context + build transposed xin + alpha/context out ----------------
// grid 64 (b), block 1024 (d)
__global__ void ctx_finalize(const int* __restrict__ X, const float* __restrict__ emb,
                             const float* __restrict__ h,
                             float* __restrict__ o_ctx, float* __restrict__ o_alpha) {
    int b = blockIdx.x, d = threadIdx.x;
    float s = 0.0f;
#pragma unroll
    for (int j = 0; j < 8; j++) s += g_pctx[((size_t)j * BB + b) * AD + d];
    o_ctx[b * AD + d]   = s;
    o_alpha[b * TXX + d] = 1.0f;
    g_xinT[d * BB + b] = s;                                   // rows 0..1023 : context
    if (d < ED) {
        int tok = X[b];
        g_xinT[(AD + d) * BB + b] = emb[(size_t)tok * ED + d]; // rows 1024..1535 : embedding
    }
    g_xinT[(AD + ED + d) * BB + b] = h[b * UN + d];            // rows 1536..2559 : h
}

// ---------------- K3: z = xin@Wx + h@Wh (K-split x4) ----------------
// grid (32 n-tiles, 4 k-chunks), block 128; thread owns one column, 64 rows packed in 32 f32x2 accs
__global__ void zgemm(const float* __restrict__ Wx, const float* __restrict__ Wh) {
    __shared__ float4 xs4[512];                 // 32 k x 64 m floats (8 KB)
    const ulonglong2* xs = (const ulonglong2*)xs4;
    int n  = blockIdx.x * 128 + threadIdx.x;
    int k0 = blockIdx.y * 640;
    ull acc[32];
#pragma unroll
    for (int i = 0; i < 32; i++) acc[i] = 0ull;

    for (int kt = k0; kt < k0 + 640; kt += 32) {
        __syncthreads();
        const float4* src = (const float4*)(g_xinT + (size_t)kt * BB);
#pragma unroll
        for (int j = 0; j < 4; j++) xs4[threadIdx.x + j * 128] = src[threadIdx.x + j * 128];
        __syncthreads();
#pragma unroll 4
        for (int kk = 0; kk < 32; kk++) {
            int k = kt + kk;
            float w = (k < AD + ED) ? __ldg(Wx + (size_t)k * NZ + n)
                                    : __ldg(Wh + (size_t)(k - (AD + ED)) * NZ + n);
            ull w2 = pack2(w, w);
            const ulonglong2* row = xs + kk * 16;
#pragma unroll
            for (int m4 = 0; m4 < 16; m4++) {
                ulonglong2 v = row[m4];
                acc[2 * m4]     = fma2(v.x, w2, acc[2 * m4]);
                acc[2 * m4 + 1] = fma2(v.y, w2, acc[2 * m4 + 1]);
            }
        }
    }
    float* zp = g_zpart + (size_t)blockIdx.y * BB * NZ;
#pragma unroll
    for (int i = 0; i < 32; i++) {
        float2 f = unpack2(acc[i]);
        zp[(size_t)(2 * i) * NZ + n]     = f.x;
        zp[(size_t)(2 * i + 1) * NZ + n] = f.y;
    }
}

// ---------------- K4: LSTM gates ----------------
// grid 64 (b), block 1024 (u). Keras gate order i,f,g,o.
__global__ void gates(const float* __restrict__ c, const float* __restrict__ bl,
                      float* __restrict__ o_h, float* __restrict__ o_c) {
    int b = blockIdx.x, u = threadIdx.x;
    float zi = bl[u], zf = bl[u + UN], zg = bl[u + 2 * UN], zo = bl[u + 3 * UN];
#pragma unroll
    for (int kc = 0; kc < 4; kc++) {
        const float* base = g_zpart + (size_t)kc * BB * NZ + (size_t)b * NZ;
        zi += base[u]; zf += base[u + UN]; zg += base[u + 2 * UN]; zo += base[u + 3 * UN];
    }
    float cn = sigf(zf) * c[b * UN + u] + sigf(zi) * tanhf(zg);
    float hn = sigf(zo) * tanhf(cn);
    o_c[b * UN + u] = cn;
    o_h[b * UN + u] = hn;
    g_hT[u * BB + b] = hn;
}

// ---------------- K5: logits = h_new @ Wv (K-split x2) ----------------
// grid (250 n-tiles, 2 k-chunks), block 128
__global__ void vgemm(const float* __restrict__ Wv) {
    __shared__ float4 xs4[512];
    const ulonglong2* xs = (const ulonglong2*)xs4;
    int n  = blockIdx.x * 128 + threadIdx.x;
    int k0 = blockIdx.y * 512;
    ull acc[32];
#pragma unroll
    for (int i = 0; i < 32; i++) acc[i] = 0ull;

    for (int kt = k0; kt < k0 + 512; kt += 32) {
        __syncthreads();
        const float4* src = (const float4*)(g_hT + (size_t)kt * BB);
#pragma unroll
        for (int j = 0; j < 4; j++) xs4[threadIdx.x + j * 128] = src[threadIdx.x + j * 128];
        __syncthreads();
#pragma unroll 4
        for (int kk = 0; kk < 32; kk++) {
            float w = __ldg(Wv + (size_t)(kt + kk) * VOC + n);
            ull w2 = pack2(w, w);
            const ulonglong2* row = xs + kk * 16;
#pragma unroll
            for (int m4 = 0; m4 < 16; m4++) {
                ulonglong2 v = row[m4];
                acc[2 * m4]     = fma2(v.x, w2, acc[2 * m4]);
                acc[2 * m4 + 1] = fma2(v.y, w2, acc[2 * m4 + 1]);
            }
        }
    }
    float* lp = g_lpart + (size_t)blockIdx.y * BB * VOC;
#pragma unroll
    for (int i = 0; i < 32; i++) {
        float2 f = unpack2(acc[i]);
        lp[(size_t)(2 * i) * VOC + n]     = f.x;
        lp[(size_t)(2 * i + 1) * VOC + n] = f.y;
    }
}

// ---------------- K6: softmax over vocab ----------------
// grid 64 (b), block 512
__global__ void softmax_k(const float* __restrict__ bv, float* __restrict__ o_y) {
    int b = blockIdx.x, tid = threadIdx.x;
    __shared__ float red[512];
    float mx = -1e30f;
    for (int n = tid; n < VOC; n += 512) {
        float l = g_lpart[(size_t)b * VOC + n]
                + g_lpart[(size_t)BB * VOC + (size_t)b * VOC + n] + bv[n];
        g_logits[(size_t)b * VOC + n] = l;
        mx = fmaxf(mx, l);
    }
    red[tid] = mx; __syncthreads();
    for (int s = 256; s > 0; s >>= 1) {
        if (tid < s) red[tid] = fmaxf(red[tid], red[tid + s]);
        __syncthreads();
    }
    float M = red[0]; __syncthreads();
    float sum = 0.0f;
    for (int n = tid; n < VOC; n += 512) sum += expf(g_logits[(size_t)b * VOC + n] - M);
    red[tid] = sum; __syncthreads();
    for (int s = 256; s > 0; s >>= 1) {
        if (tid < s) red[tid] += red[tid + s];
        __syncthreads();
    }
    float inv = 1.0f / red[0]; __syncthreads();
    for (int n = tid; n < VOC; n += 512)
        o_y[(size_t)b * VOC + n] = expf(g_logits[(size_t)b * VOC + n] - M) * inv;
}

// ---------------- launch ----------------
extern "C" void kernel_launch(void* const* d_in, const int* in_sizes, int n_in,
                              void* d_out, int out_size) {
    (void)in_sizes; (void)n_in; (void)out_size;
    const int*   X   = (const int*)d_in[0];
    const float* a   = (const float*)d_in[1];
    const float* h   = (const float*)d_in[2];
    const float* c   = (const float*)d_in[3];
    const float* emb = (const float*)d_in[4];
    // d_in[5..10] = W1,b1,W2,b2,We,be : dead code (softmax over size-1 axis == 1)
    const float* Wx  = (const float*)d_in[11];
    const float* Wh  = (const float*)d_in[12];
    const float* bl  = (const float*)d_in[13];
    const float* Wv  = (const float*)d_in[14];
    const float* bv  = (const float*)d_in[15];

    float* out     = (float*)d_out;
    float* o_y     = out;                    // [64, 32000]
    float* o_ctx   = o_y + (size_t)BB * VOC; // [64, 1, 1024]
    float* o_alpha = o_ctx + BB * AD;        // [64, 1024]
    float* o_h     = o_alpha + BB * TXX;     // [64, 1024]
    float* o_c     = o_h + BB * UN;          // [64, 1024]

    ctx_partial<<<dim3(4, 8, 64), 256>>>(a);
    ctx_finalize<<<64, 1024>>>(X, emb, h, o_ctx, o_alpha);
    zgemm<<<dim3(32, 4), 128>>>(Wx, Wh);
    gates<<<64, 1024>>>(c, bl, o_h, o_c);
    vgemm<<<dim3(250, 2), 128>>>(Wv);
    softmax_k<<<64, 512>>>(bv, o_y);
}

// round 5
// speedup vs baseline: 2.3660x; 2.3660x over previous
#include <cuda_runtime.h>
#include <cuda_bf16.h>
#include <mma.h>

using namespace nvcuda;

#define BB    64
#define TXX   1024
#define AD    1024
#define UN    1024
#define VOC   32000
#define ED    512
#define KXIN  2560
#define NZ    4096
#define ZSPLITS 4

#define TP 72         // smem tile pitch (bf16 elems), 144 B = mult of 16 B

// ---------------- scratch (__device__ globals; NEVER passed from host) ----------------
__device__ __align__(16) float g_pctx[8 * BB * AD];
__device__ __align__(16) __nv_bfloat16 g_xz_hi[BB * KXIN];
__device__ __align__(16) __nv_bfloat16 g_xz_lo[BB * KXIN];
__device__ __align__(16) __nv_bfloat16 g_xv_hi[BB * UN];
__device__ __align__(16) __nv_bfloat16 g_xv_lo[BB * UN];
__device__ __align__(16) float g_zpart[ZSPLITS * BB * NZ];
__device__ __align__(16) float g_logits[BB * VOC];

__device__ __forceinline__ float sigf(float x) { return 1.0f / (1.0f + __expf(-x)); }

__device__ __forceinline__ void split_write(__nv_bfloat16* hi, __nv_bfloat16* lo,
                                            size_t idx, float v) {
    __nv_bfloat16 h = __float2bfloat16(v);
    hi[idx] = h;
    lo[idx] = __float2bfloat16(v - __bfloat162float(h));
}

// ---------------- K1: context partial sums ----------------
__global__ void ctx_partial(const float* __restrict__ a) {
    int d4 = threadIdx.x;                 // 0..255 (float4 lanes)
    int b  = blockIdx.y;
    int t0 = blockIdx.x * 128;
    const float4* p = (const float4*)(a + ((size_t)b * TXX + t0) * AD) + d4;
    float4 s = make_float4(0.f, 0.f, 0.f, 0.f);
#pragma unroll 8
    for (int t = 0; t < 128; t++) {
        float4 v = p[(size_t)t * 256];
        s.x += v.x; s.y += v.y; s.z += v.z; s.w += v.w;
    }
    ((float4*)g_pctx)[((size_t)blockIdx.x * BB + b) * 256 + d4] = s;
}

// ---------------- K2: finalize ctx + build xin bf16 hi/lo images ----------------
__global__ void ctx_finalize(const int* __restrict__ X, const float* __restrict__ emb,
                             const float* __restrict__ h,
                             float* __restrict__ o_ctx, float* __restrict__ o_alpha) {
    int b = blockIdx.x, d = threadIdx.x;
    float s = 0.f;
#pragma unroll
    for (int j = 0; j < 8; j++) s += g_pctx[((size_t)j * BB + b) * AD + d];
    o_ctx[b * AD + d]    = s;
    o_alpha[b * TXX + d] = 1.0f;
    size_t row = (size_t)b * KXIN;
    split_write(g_xz_hi, g_xz_lo, row + d, s);                     // k [0,1024)
    if (d < ED) {
        int tok = X[b];
        split_write(g_xz_hi, g_xz_lo, row + AD + d, emb[(size_t)tok * ED + d]);
    }
    split_write(g_xz_hi, g_xz_lo, row + AD + ED + d, h[b * UN + d]);
}

// ---------------- wmma GEMM: out[64,...] = x[64,K] @ W[K,N]  (bf16 hi/lo split) ----------------
// 128 thr = 4 warps; tile 64m x 64n; K chunk 64; static smem 36864 B.
// in_sel/out_sel pick the __device__ scratch symbols INSIDE device code.
__global__ void __launch_bounds__(128)
wgemm(const float* __restrict__ Wa, const float* __restrict__ Wb, int kbound, int ldw,
      int in_sel, int ldx, int nchunks, int out_sel, int ldo) {
    __shared__ __align__(32) __nv_bfloat16 sm[4 * 64 * TP];
    __nv_bfloat16* Ah = sm;
    __nv_bfloat16* Al = sm + 4608;
    __nv_bfloat16* Bh = sm + 9216;
    __nv_bfloat16* Bl = sm + 13824;

    const __nv_bfloat16* xhi = in_sel ? g_xv_hi : g_xz_hi;
    const __nv_bfloat16* xlo = in_sel ? g_xv_lo : g_xz_lo;

    int tid = threadIdx.x, w = tid >> 5;
    int n0 = blockIdx.x * 64;
    int k0 = blockIdx.y * nchunks * 64;
    float* out = out_sel ? g_logits : (g_zpart + (size_t)blockIdx.y * BB * NZ);

    wmma::fragment<wmma::accumulator, 16, 16, 16, float> acc[4];
#pragma unroll
    for (int i = 0; i < 4; i++) wmma::fill_fragment(acc[i], 0.0f);

    for (int ci = 0; ci < nchunks; ci++) {
        int kg0 = k0 + ci * 64;
        __syncthreads();
        // --- A: 64 rows x 64 k, hi/lo (512 uint4 each) ---
#pragma unroll
        for (int i = 0; i < 4; i++) {
            int idx = tid + i * 128;
            int row = idx >> 3, j = idx & 7;
            size_t so = ((size_t)row * ldx + kg0) / 8 + j;
            ((uint4*)Ah)[row * 9 + j] = ((const uint4*)xhi)[so];
            ((uint4*)Al)[row * 9 + j] = ((const uint4*)xlo)[so];
        }
        // --- B: 64 k x 64 n fp32 -> bf16 hi/lo ---
#pragma unroll
        for (int i = 0; i < 8; i++) {
            int idx = tid + i * 128;
            int k = idx >> 4, f4c = idx & 15;
            int kg = kg0 + k;
            const float* wrow = (kg < kbound) ? (Wa + (size_t)kg * ldw)
                                              : (Wb + (size_t)(kg - kbound) * ldw);
            float4 v = __ldg((const float4*)(wrow + n0) + f4c);
            __nv_bfloat16 h0 = __float2bfloat16(v.x), h1 = __float2bfloat16(v.y);
            __nv_bfloat16 h2 = __float2bfloat16(v.z), h3 = __float2bfloat16(v.w);
            __nv_bfloat16 l0 = __float2bfloat16(v.x - __bfloat162float(h0));
            __nv_bfloat16 l1 = __float2bfloat16(v.y - __bfloat162float(h1));
            __nv_bfloat16 l2 = __float2bfloat16(v.z - __bfloat162float(h2));
            __nv_bfloat16 l3 = __float2bfloat16(v.w - __bfloat162float(h3));
            int bo = k * TP + f4c * 4;
            *(__nv_bfloat162*)(Bh + bo)     = __halves2bfloat162(h0, h1);
            *(__nv_bfloat162*)(Bh + bo + 2) = __halves2bfloat162(h2, h3);
            *(__nv_bfloat162*)(Bl + bo)     = __halves2bfloat162(l0, l1);
            *(__nv_bfloat162*)(Bl + bo + 2) = __halves2bfloat162(l2, l3);
        }
        __syncthreads();
        // --- compute: warp w owns n-strip [w*16, w*16+16) ---
#pragma unroll
        for (int kt = 0; kt < 4; kt++) {
            wmma::fragment<wmma::matrix_b, 16, 16, 16, __nv_bfloat16, wmma::row_major> bh, bl;
            wmma::load_matrix_sync(bh, Bh + kt * 16 * TP + w * 16, TP);
            wmma::load_matrix_sync(bl, Bl + kt * 16 * TP + w * 16, TP);
#pragma unroll
            for (int mt = 0; mt < 4; mt++) {
                wmma::fragment<wmma::matrix_a, 16, 16, 16, __nv_bfloat16, wmma::row_major> ah, al;
                wmma::load_matrix_sync(ah, Ah + mt * 16 * TP + kt * 16, TP);
                wmma::load_matrix_sync(al, Al + mt * 16 * TP + kt * 16, TP);
                wmma::mma_sync(acc[mt], ah, bh, acc[mt]);
                wmma::mma_sync(acc[mt], ah, bl, acc[mt]);
                wmma::mma_sync(acc[mt], al, bh, acc[mt]);
            }
        }
    }
#pragma unroll
    for (int mt = 0; mt < 4; mt++)
        wmma::store_matrix_sync(out + (size_t)(mt * 16) * ldo + n0 + w * 16,
                                acc[mt], ldo, wmma::mem_row_major);
}

// ---------------- K4: LSTM gates + h_new bf16 images ----------------
__global__ void gates(const float* __restrict__ c, const float* __restrict__ bl,
                      float* __restrict__ o_h, float* __restrict__ o_c) {
    int b = blockIdx.x, u = threadIdx.x;
    float zi = bl[u], zf = bl[u + UN], zg = bl[u + 2 * UN], zo = bl[u + 3 * UN];
#pragma unroll
    for (int s = 0; s < ZSPLITS; s++) {
        const float* zp = g_zpart + (size_t)s * BB * NZ + (size_t)b * NZ;
        zi += zp[u]; zf += zp[u + UN]; zg += zp[u + 2 * UN]; zo += zp[u + 3 * UN];
    }
    float cn = sigf(zf) * c[b * UN + u] + sigf(zi) * tanhf(zg);
    float hn = sigf(zo) * tanhf(cn);
    o_c[b * UN + u] = cn;
    o_h[b * UN + u] = hn;
    split_write(g_xv_hi, g_xv_lo, (size_t)b * UN + u, hn);
}

// ---------------- K6: softmax over vocab ----------------
__global__ void softmax_k(const float* __restrict__ bv, float* __restrict__ o_y) {
    int b = blockIdx.x, tid = threadIdx.x;
    __shared__ float red[1024];
    const float* lg = g_logits + (size_t)b * VOC;
    float mx = -1e30f;
    for (int n = tid; n < VOC; n += 1024) mx = fmaxf(mx, lg[n] + bv[n]);
    red[tid] = mx; __syncthreads();
    for (int s = 512; s > 0; s >>= 1) {
        if (tid < s) red[tid] = fmaxf(red[tid], red[tid + s]);
        __syncthreads();
    }
    float M = red[0]; __syncthreads();
    float sum = 0.f;
    for (int n = tid; n < VOC; n += 1024) sum += __expf(lg[n] + bv[n] - M);
    red[tid] = sum; __syncthreads();
    for (int s = 512; s > 0; s >>= 1) {
        if (tid < s) red[tid] += red[tid + s];
        __syncthreads();
    }
    float inv = 1.0f / red[0];
    for (int n = tid; n < VOC; n += 1024)
        o_y[(size_t)b * VOC + n] = __expf(lg[n] + bv[n] - M) * inv;
}

// ---------------- launch ----------------
extern "C" void kernel_launch(void* const* d_in, const int* in_sizes, int n_in,
                              void* d_out, int out_size) {
    (void)in_sizes; (void)n_in; (void)out_size;
    const int*   X   = (const int*)d_in[0];
    const float* a   = (const float*)d_in[1];
    const float* h   = (const float*)d_in[2];
    const float* c   = (const float*)d_in[3];
    const float* emb = (const float*)d_in[4];
    // d_in[5..10] dead (softmax over size-1 axis == 1)
    const float* Wx  = (const float*)d_in[11];
    const float* Wh  = (const float*)d_in[12];
    const float* bl  = (const float*)d_in[13];
    const float* Wv  = (const float*)d_in[14];
    const float* bv  = (const float*)d_in[15];

    float* out     = (float*)d_out;
    float* o_y     = out;
    float* o_ctx   = o_y + (size_t)BB * VOC;
    float* o_alpha = o_ctx + BB * AD;
    float* o_h     = o_alpha + BB * TXX;
    float* o_c     = o_h + BB * UN;

    ctx_partial<<<dim3(8, 64), 256>>>(a);
    ctx_finalize<<<64, 1024>>>(X, emb, h, o_ctx, o_alpha);
    // z = xin@[Wx;Wh] : K=2560 = 4 splits x 10 chunks of 64; 64 n-blocks
    wgemm<<<dim3(NZ / 64, ZSPLITS), 128>>>(
        Wx, Wh, AD + ED, NZ, /*in_sel=*/0, KXIN, (KXIN / 64) / ZSPLITS, /*out_sel=*/0, NZ);
    gates<<<64, 1024>>>(c, bl, o_h, o_c);
    // logits = h_new@Wv : K=1024 = 16 chunks of 64; 500 n-blocks
    wgemm<<<dim3(VOC / 64, 1), 128>>>(
        Wv, Wv, 0x7fffffff, VOC, /*in_sel=*/1, UN, UN / 64, /*out_sel=*/1, VOC);
    softmax_k<<<64, 1024>>>(bv, o_y);
}

// round 6
// speedup vs baseline: 2.7115x; 1.1460x over previous
#include <cuda_runtime.h>
#include <cuda_bf16.h>
#include <mma.h>

using namespace nvcuda;

#define BB    64
#define TXX   1024
#define AD    1024
#define UN    1024
#define VOC   32000
#define ED    512
#define KXIN  2560
#define NZ    4096
#define ZSPLITS 4

#define TP 72         // smem tile pitch (bf16 elems), 144 B = mult of 16 B

// ---------------- scratch (__device__ globals; NEVER passed from host) ----------------
__device__ __align__(16) float g_pctx[8 * BB * AD];
__device__ __align__(16) __nv_bfloat16 g_xz_hi[BB * KXIN];
__device__ __align__(16) __nv_bfloat16 g_xz_lo[BB * KXIN];
__device__ __align__(16) __nv_bfloat16 g_xv_hi[BB * UN];
__device__ __align__(16) __nv_bfloat16 g_xv_lo[BB * UN];
__device__ __align__(16) float g_zpart[ZSPLITS * BB * NZ];
__device__ __align__(16) float g_logits[BB * VOC];

__device__ __forceinline__ float sigf(float x) { return 1.0f / (1.0f + __expf(-x)); }

__device__ __forceinline__ void split_write(__nv_bfloat16* hi, __nv_bfloat16* lo,
                                            size_t idx, float v) {
    __nv_bfloat16 h = __float2bfloat16(v);
    hi[idx] = h;
    lo[idx] = __float2bfloat16(v - __bfloat162float(h));
}

// ---------------- K1: context partial sums ----------------
__global__ void ctx_partial(const float* __restrict__ a) {
    int d4 = threadIdx.x;                 // 0..255 (float4 lanes)
    int b  = blockIdx.y;
    int t0 = blockIdx.x * 128;
    const float4* p = (const float4*)(a + ((size_t)b * TXX + t0) * AD) + d4;
    float4 s = make_float4(0.f, 0.f, 0.f, 0.f);
#pragma unroll 8
    for (int t = 0; t < 128; t++) {
        float4 v = p[(size_t)t * 256];
        s.x += v.x; s.y += v.y; s.z += v.z; s.w += v.w;
    }
    ((float4*)g_pctx)[((size_t)blockIdx.x * BB + b) * 256 + d4] = s;
}

// ---------------- K2: finalize ctx + build xin bf16 hi/lo images ----------------
// grid (4 d-chunks, 64 b), block 256
__global__ void ctx_finalize(const int* __restrict__ X, const float* __restrict__ emb,
                             const float* __restrict__ h,
                             float* __restrict__ o_ctx, float* __restrict__ o_alpha) {
    int b = blockIdx.y;
    int d = blockIdx.x * 256 + threadIdx.x;
    float s = 0.f;
#pragma unroll
    for (int j = 0; j < 8; j++) s += g_pctx[((size_t)j * BB + b) * AD + d];
    o_ctx[b * AD + d]    = s;
    o_alpha[b * TXX + d] = 1.0f;
    size_t row = (size_t)b * KXIN;
    split_write(g_xz_hi, g_xz_lo, row + d, s);                     // k [0,1024)
    if (d < ED) {
        int tok = X[b];
        split_write(g_xz_hi, g_xz_lo, row + AD + d, emb[(size_t)tok * ED + d]);
    }
    split_write(g_xz_hi, g_xz_lo, row + AD + ED + d, h[b * UN + d]);
}

// ---------------- wmma GEMM: out[64,...] = x[64,K] @ W[K,N]  (bf16 hi/lo split) ----------------
// 128 thr = 4 warps; tile 64m x 64n; K chunk 64; static smem 36864 B.
// B (DRAM) is register-prefetched one chunk ahead; mma reordered into 3 passes
// over 4 independent accumulators to break HMMA dependency chains.
__global__ void __launch_bounds__(128, 4)
wgemm(const float* __restrict__ Wa, const float* __restrict__ Wb, int kbound, int ldw,
      int in_sel, int ldx, int nchunks, int out_sel, int ldo) {
    __shared__ __align__(32) __nv_bfloat16 sm[4 * 64 * TP];
    __nv_bfloat16* Ah = sm;
    __nv_bfloat16* Al = sm + 4608;
    __nv_bfloat16* Bh = sm + 9216;
    __nv_bfloat16* Bl = sm + 13824;

    const __nv_bfloat16* xhi = in_sel ? g_xv_hi : g_xz_hi;
    const __nv_bfloat16* xlo = in_sel ? g_xv_lo : g_xz_lo;

    int tid = threadIdx.x, w = tid >> 5;
    int n0 = blockIdx.x * 64;
    int k0 = blockIdx.y * nchunks * 64;
    float* out = out_sel ? g_logits : (g_zpart + (size_t)blockIdx.y * BB * NZ);

    wmma::fragment<wmma::accumulator, 16, 16, 16, float> acc[4];
#pragma unroll
    for (int i = 0; i < 4; i++) wmma::fill_fragment(acc[i], 0.0f);

    float4 pf[8];
    auto ldB = [&](int kg0) {
#pragma unroll
        for (int i = 0; i < 8; i++) {
            int idx = tid + i * 128;
            int k = idx >> 4, f4c = idx & 15;
            int kg = kg0 + k;
            const float* wrow = (kg < kbound) ? (Wa + (size_t)kg * ldw)
                                              : (Wb + (size_t)(kg - kbound) * ldw);
            pf[i] = __ldg((const float4*)(wrow + n0) + f4c);
        }
    };

    ldB(k0);                                   // prefetch chunk 0
    for (int ci = 0; ci < nchunks; ci++) {
        int kg0 = k0 + ci * 64;
        __syncthreads();
        // --- A: 64 rows x 64 k, hi/lo (512 uint4 each; L2-resident) ---
#pragma unroll
        for (int i = 0; i < 4; i++) {
            int idx = tid + i * 128;
            int row = idx >> 3, j = idx & 7;
            size_t so = ((size_t)row * ldx + kg0) / 8 + j;
            ((uint4*)Ah)[row * 9 + j] = ((const uint4*)xhi)[so];
            ((uint4*)Al)[row * 9 + j] = ((const uint4*)xlo)[so];
        }
        // --- B: convert prefetched fp32 regs -> bf16 hi/lo smem tiles ---
#pragma unroll
        for (int i = 0; i < 8; i++) {
            int idx = tid + i * 128;
            int k = idx >> 4, f4c = idx & 15;
            float4 v = pf[i];
            __nv_bfloat16 h0 = __float2bfloat16(v.x), h1 = __float2bfloat16(v.y);
            __nv_bfloat16 h2 = __float2bfloat16(v.z), h3 = __float2bfloat16(v.w);
            __nv_bfloat16 l0 = __float2bfloat16(v.x - __bfloat162float(h0));
            __nv_bfloat16 l1 = __float2bfloat16(v.y - __bfloat162float(h1));
            __nv_bfloat16 l2 = __float2bfloat16(v.z - __bfloat162float(h2));
            __nv_bfloat16 l3 = __float2bfloat16(v.w - __bfloat162float(h3));
            int bo = k * TP + f4c * 4;
            *(__nv_bfloat162*)(Bh + bo)     = __halves2bfloat162(h0, h1);
            *(__nv_bfloat162*)(Bh + bo + 2) = __halves2bfloat162(h2, h3);
            *(__nv_bfloat162*)(Bl + bo)     = __halves2bfloat162(l0, l1);
            *(__nv_bfloat162*)(Bl + bo + 2) = __halves2bfloat162(l2, l3);
        }
        __syncthreads();
        if (ci + 1 < nchunks) ldB(kg0 + 64);   // prefetch next chunk (hidden by mma)
        // --- compute: warp w owns n-strip [w*16, w*16+16) ---
#pragma unroll
        for (int kt = 0; kt < 4; kt++) {
            wmma::fragment<wmma::matrix_b, 16, 16, 16, __nv_bfloat16, wmma::row_major> bh, bl;
            wmma::load_matrix_sync(bh, Bh + kt * 16 * TP + w * 16, TP);
            wmma::load_matrix_sync(bl, Bl + kt * 16 * TP + w * 16, TP);
            wmma::fragment<wmma::matrix_a, 16, 16, 16, __nv_bfloat16, wmma::row_major> af[4];
#pragma unroll
            for (int mt = 0; mt < 4; mt++)
                wmma::load_matrix_sync(af[mt], Ah + mt * 16 * TP + kt * 16, TP);
#pragma unroll
            for (int mt = 0; mt < 4; mt++) wmma::mma_sync(acc[mt], af[mt], bh, acc[mt]);
#pragma unroll
            for (int mt = 0; mt < 4; mt++) wmma::mma_sync(acc[mt], af[mt], bl, acc[mt]);
#pragma unroll
            for (int mt = 0; mt < 4; mt++)
                wmma::load_matrix_sync(af[mt], Al + mt * 16 * TP + kt * 16, TP);
#pragma unroll
            for (int mt = 0; mt < 4; mt++) wmma::mma_sync(acc[mt], af[mt], bh, acc[mt]);
        }
    }
#pragma unroll
    for (int mt = 0; mt < 4; mt++)
        wmma::store_matrix_sync(out + (size_t)(mt * 16) * ldo + n0 + w * 16,
                                acc[mt], ldo, wmma::mem_row_major);
}

// ---------------- K4: LSTM gates + h_new bf16 images ----------------
// grid (4 u-chunks, 64 b), block 256
__global__ void gates(const float* __restrict__ c, const float* __restrict__ bl,
                      float* __restrict__ o_h, float* __restrict__ o_c) {
    int b = blockIdx.y;
    int u = blockIdx.x * 256 + threadIdx.x;
    float zi = bl[u], zf = bl[u + UN], zg = bl[u + 2 * UN], zo = bl[u + 3 * UN];
#pragma unroll
    for (int s = 0; s < ZSPLITS; s++) {
        const float* zp = g_zpart + (size_t)s * BB * NZ + (size_t)b * NZ;
        zi += zp[u]; zf += zp[u + UN]; zg += zp[u + 2 * UN]; zo += zp[u + 3 * UN];
    }
    float cn = sigf(zf) * c[b * UN + u] + sigf(zi) * tanhf(zg);
    float hn = sigf(zo) * tanhf(cn);
    o_c[b * UN + u] = cn;
    o_h[b * UN + u] = hn;
    split_write(g_xv_hi, g_xv_lo, (size_t)b * UN + u, hn);
}

// ---------------- K6: softmax over vocab (float4) ----------------
__global__ void softmax_k(const float* __restrict__ bv, float* __restrict__ o_y) {
    int b = blockIdx.x, tid = threadIdx.x;
    __shared__ float red[1024];
    const float4* lg4 = (const float4*)(g_logits + (size_t)b * VOC);
    const float4* bv4 = (const float4*)bv;
    float4* oy4 = (float4*)(o_y + (size_t)b * VOC);
    float mx = -1e30f;
    for (int n = tid; n < VOC / 4; n += 1024) {
        float4 l = lg4[n], v = bv4[n];
        mx = fmaxf(mx, fmaxf(fmaxf(l.x + v.x, l.y + v.y), fmaxf(l.z + v.z, l.w + v.w)));
    }
    red[tid] = mx; __syncthreads();
    for (int s = 512; s > 0; s >>= 1) {
        if (tid < s) red[tid] = fmaxf(red[tid], red[tid + s]);
        __syncthreads();
    }
    float M = red[0]; __syncthreads();
    float sum = 0.f;
    for (int n = tid; n < VOC / 4; n += 1024) {
        float4 l = lg4[n], v = bv4[n];
        float4 e = make_float4(__expf(l.x + v.x - M), __expf(l.y + v.y - M),
                               __expf(l.z + v.z - M), __expf(l.w + v.w - M));
        oy4[n] = e;
        sum += e.x + e.y + e.z + e.w;
    }
    red[tid] = sum; __syncthreads();
    for (int s = 512; s > 0; s >>= 1) {
        if (tid < s) red[tid] += red[tid + s];
        __syncthreads();
    }
    float inv = 1.0f / red[0];
    for (int n = tid; n < VOC / 4; n += 1024) {
        float4 e = oy4[n];
        e.x *= inv; e.y *= inv; e.z *= inv; e.w *= inv;
        oy4[n] = e;
    }
}

// ---------------- launch ----------------
extern "C" void kernel_launch(void* const* d_in, const int* in_sizes, int n_in,
                              void* d_out, int out_size) {
    (void)in_sizes; (void)n_in; (void)out_size;
    const int*   X   = (const int*)d_in[0];
    const float* a   = (const float*)d_in[1];
    const float* h   = (const float*)d_in[2];
    const float* c   = (const float*)d_in[3];
    const float* emb = (const float*)d_in[4];
    // d_in[5..10] dead (softmax over size-1 axis == 1)
    const float* Wx  = (const float*)d_in[11];
    const float* Wh  = (const float*)d_in[12];
    const float* bl  = (const float*)d_in[13];
    const float* Wv  = (const float*)d_in[14];
    const float* bv  = (const float*)d_in[15];

    float* out     = (float*)d_out;
    float* o_y     = out;
    float* o_ctx   = o_y + (size_t)BB * VOC;
    float* o_alpha = o_ctx + BB * AD;
    float* o_h     = o_alpha + BB * TXX;
    float* o_c     = o_h + BB * UN;

    ctx_partial<<<dim3(8, 64), 256>>>(a);
    ctx_finalize<<<dim3(4, 64), 256>>>(X, emb, h, o_ctx, o_alpha);
    // z = xin@[Wx;Wh] : K=2560 = 4 splits x 10 chunks of 64; 64 n-blocks
    wgemm<<<dim3(NZ / 64, ZSPLITS), 128>>>(
        Wx, Wh, AD + ED, NZ, /*in_sel=*/0, KXIN, (KXIN / 64) / ZSPLITS, /*out_sel=*/0, NZ);
    gates<<<dim3(4, 64), 256>>>(c, bl, o_h, o_c);
    // logits = h_new@Wv : K=1024 = 16 chunks of 64; 500 n-blocks
    wgemm<<<dim3(VOC / 64, 1), 128>>>(
        Wv, Wv, 0x7fffffff, VOC, /*in_sel=*/1, UN, UN / 64, /*out_sel=*/1, VOC);
    softmax_k<<<64, 1024>>>(bv, o_y);
}